// round 9
// baseline (speedup 1.0000x reference)
#include <cuda_runtime.h>
#include <cstdint>
#include <math.h>

#define B_SZ  32
#define T_LEN 2048
#define I_DIM 128
#define H_DIM 256
#define N_TOK (B_SZ * T_LEN)   // 65536

// Scratch (device globals: allocation-free rule)
__device__ float g_xB[(size_t)N_TOK * H_DIM];   // 64 MB
__device__ float g_hs[(size_t)N_TOK * H_DIM];   // 64 MB

// ---------------------------------------------------------------------------
// helpers
// ---------------------------------------------------------------------------
__device__ __forceinline__ uint32_t smem_u32(const void* p) {
    uint32_t a;
    asm("{ .reg .u64 t; cvta.to.shared.u64 t, %1; cvt.u32.u64 %0, t; }"
        : "=r"(a) : "l"(p));
    return a;
}
__device__ __forceinline__ void mbar_wait(uint32_t mbar, uint32_t parity) {
    asm volatile(
        "{\n\t.reg .pred P;\n\t"
        "WAITLOOP_%=:\n\t"
        "mbarrier.try_wait.parity.acquire.cta.shared::cta.b64 P, [%0], %1, 0x989680;\n\t"
        "@P bra.uni WAITDONE_%=;\n\t"
        "bra.uni WAITLOOP_%=;\n\t"
        "WAITDONE_%=:\n\t}"
        :: "r"(mbar), "r"(parity) : "memory");
}

// ---------------------------------------------------------------------------
// fp32 tiled GEMM (scalar FFMA): Y[M,N] = X[M,K] @ W[K,N]
// BM=128, BN=64, BK=16, 256 threads, 8x4 micro-tile per thread.
// ---------------------------------------------------------------------------
__global__ void __launch_bounds__(256) gemm_kernel(const float* __restrict__ X,
                                                   const float* __restrict__ W,
                                                   float* __restrict__ Y,
                                                   int M, int K, int N) {
    __shared__ float Xs[16][128];
    __shared__ float Ws[16][64];

    const int tid = threadIdx.x;
    const int m0 = blockIdx.x * 128;
    const int n0 = blockIdx.y * 64;
    const int tx = tid & 15;
    const int ty = tid >> 4;

    float acc[8][4];
#pragma unroll
    for (int r = 0; r < 8; r++)
#pragma unroll
        for (int cc = 0; cc < 4; cc++) acc[r][cc] = 0.f;

    const int lrow  = tid >> 1;
    const int lpart = (tid & 1) * 8;

    for (int kt = 0; kt < K; kt += 16) {
        const float* xp = X + (size_t)(m0 + lrow) * K + kt + lpart;
        float4 v0 = *(const float4*)(xp);
        float4 v1 = *(const float4*)(xp + 4);
        Xs[lpart + 0][lrow] = v0.x;
        Xs[lpart + 1][lrow] = v0.y;
        Xs[lpart + 2][lrow] = v0.z;
        Xs[lpart + 3][lrow] = v0.w;
        Xs[lpart + 4][lrow] = v1.x;
        Xs[lpart + 5][lrow] = v1.y;
        Xs[lpart + 6][lrow] = v1.z;
        Xs[lpart + 7][lrow] = v1.w;
        {
            const int wk = tid >> 4;
            const int wn = (tid & 15) * 4;
            float4 wv = *(const float4*)(W + (size_t)(kt + wk) * N + n0 + wn);
            *(float4*)&Ws[wk][wn] = wv;
        }
        __syncthreads();

#pragma unroll
        for (int k = 0; k < 16; k++) {
            float4 xa = *(const float4*)&Xs[k][ty * 8];
            float4 xb = *(const float4*)&Xs[k][ty * 8 + 4];
            float4 wv = *(const float4*)&Ws[k][tx * 4];
            float xr[8] = {xa.x, xa.y, xa.z, xa.w, xb.x, xb.y, xb.z, xb.w};
            float wr[4] = {wv.x, wv.y, wv.z, wv.w};
#pragma unroll
            for (int r = 0; r < 8; r++)
#pragma unroll
                for (int cc = 0; cc < 4; cc++)
                    acc[r][cc] = fmaf(xr[r], wr[cc], acc[r][cc]);
        }
        __syncthreads();
    }

#pragma unroll
    for (int r = 0; r < 8; r++) {
        float4 o = make_float4(acc[r][0], acc[r][1], acc[r][2], acc[r][3]);
        *(float4*)&Y[(size_t)(m0 + ty * 8 + r) * N + n0 + tx * 4] = o;
    }
}

// ---------------------------------------------------------------------------
// Scan kernel: 2-CTA cluster per batch (64 CTAs). CTA owns cols
// [rank*128, rank*128+128). Thread (g = tid>>2, c = tid&3):
//   col = rank*128 + g
//   local  k-window: [rank*128     + 32c, +32)  -> ready after local barrier
//   peer   k-window: [(1-rank)*128 + 32c, +32)  -> gated by mbarrier
// A slice (64 floats) fully in registers. Per step: phase-1 FMAs over the
// local half (peer h in flight), mid-step mbar wait, phase-2 over peer half.
// h exchanged via st.async.shared::cluster (128 x 4B, complete_tx) -- no
// proxy fence, no bulk-copy launch on the critical path.
// Skew: 32-float block + 4 pad (36) => the 4 c-window reads per warp instr
// land on banks {0,4,8,12}: one phase per LDS.128, broadcast across g.
// ---------------------------------------------------------------------------
#define HSK 288                       // 8 blocks * 36 floats per buffer
#define TX_BYTES 512                  // 128 peer floats per step

__global__ void __launch_bounds__(512, 1) __cluster_dims__(2, 1, 1)
scan_kernel(const float* __restrict__ A) {
    __shared__ __align__(16) float hbuf[2][HSK];
    __shared__ __align__(8) unsigned long long bars[2];

    const int tid = threadIdx.x;
    uint32_t rank;
    asm("mov.u32 %0, %%cluster_ctarank;" : "=r"(rank));
    const int b   = blockIdx.x >> 1;
    const int g   = tid >> 2;            // 0..127
    const int c   = tid & 3;             // 0..3
    const int col = (int)rank * 128 + g;
    const int kl0 = (int)rank * 128 + c * 32;          // local-half window
    const int kp0 = (int)(rank ^ 1u) * 128 + c * 32;   // peer-half window

    // A slice fully into registers
    float a_loc[32], a_peer[32];
    {
        const float* Al = A + (size_t)kl0 * H_DIM + col;
        const float* Ap = A + (size_t)kp0 * H_DIM + col;
#pragma unroll
        for (int k = 0; k < 32; k++) a_loc[k]  = Al[(size_t)k * H_DIM];
#pragma unroll
        for (int k = 0; k < 32; k++) a_peer[k] = Ap[(size_t)k * H_DIM];
    }

    const uint32_t bar_u32[2] = { smem_u32(&bars[0]), smem_u32(&bars[1]) };
    if (tid == 0) {
        asm volatile("mbarrier.init.shared.b64 [%0], 1;" :: "r"(bar_u32[0]) : "memory");
        asm volatile("mbarrier.init.shared.b64 [%0], 1;" :: "r"(bar_u32[1]) : "memory");
    }
    // h0 = 0
    for (int i = tid; i < 2 * HSK; i += 512) ((float*)hbuf)[i] = 0.f;
    __syncthreads();
    // cluster-wide: mbarriers + zeroed h visible before any peer traffic
    asm volatile("barrier.cluster.arrive.aligned;" ::: "memory");
    asm volatile("barrier.cluster.wait.aligned;" ::: "memory");

    // skewed slot for my column (same index in my and peer's buffers)
    const int wr_idx = (col >> 5) * 36 + (col & 31);
    // peer addresses for my column's slot in both buffers + peer bars
    uint32_t p_addr[2], p_bar[2];
    {
        const uint32_t prank = rank ^ 1u;
#pragma unroll
        for (int i = 0; i < 2; i++) {
            uint32_t sa = smem_u32(&hbuf[i][wr_idx]);
            asm("mapa.shared::cluster.u32 %0, %1, %2;" : "=r"(p_addr[i]) : "r"(sa), "r"(prank));
            asm("mapa.shared::cluster.u32 %0, %1, %2;" : "=r"(p_bar[i]) : "r"(bar_u32[i]), "r"(prank));
        }
    }

    const float* xB = g_xB + (size_t)b * T_LEN * H_DIM;
    float*       hs = g_hs + (size_t)b * T_LEN * H_DIM;
    // block bases for my two read windows (constant across steps)
    const int loc_off  = ((int)rank * 4 + c) * 36;
    const int peer_off = ((int)(rank ^ 1u) * 4 + c) * 36;

    float xb_cur = (c == 0) ? xB[col] : 0.f;

    for (int s = 0; s < T_LEN; s++) {
        const int rb = s & 1, wb = rb ^ 1;

        // expect peer's 512 B into hbuf[wb] during this step
        if (tid == 0 && s + 1 < T_LEN)
            asm volatile("mbarrier.arrive.expect_tx.shared.b64 _, [%0], %1;"
                         :: "r"(bar_u32[wb]), "r"((uint32_t)TX_BYTES) : "memory");

        float xb_nxt = xb_cur;
        if (c == 0 && s + 1 < T_LEN)
            xb_nxt = xB[(size_t)(s + 1) * H_DIM + col];

        // ---- phase 1: local half (ready since last __syncthreads) ----
        const float4* hl = (const float4*)(&hbuf[rb][loc_off]);
        float acc0 = 0.f, acc1 = 0.f;
#pragma unroll
        for (int q = 0; q < 8; q++) {
            float4 hv = hl[q];
            acc0 = fmaf(hv.x, a_loc[4 * q + 0], acc0);
            acc1 = fmaf(hv.y, a_loc[4 * q + 1], acc1);
            acc0 = fmaf(hv.z, a_loc[4 * q + 2], acc0);
            acc1 = fmaf(hv.w, a_loc[4 * q + 3], acc1);
        }

        // ---- wait for peer half of hbuf[rb] (sent during step s-1) ----
        if (s > 0)
            mbar_wait(bar_u32[rb], (uint32_t)(((s - 1) >> 1) & 1));

        // ---- phase 2: peer half ----
        const float4* hp = (const float4*)(&hbuf[rb][peer_off]);
#pragma unroll
        for (int q = 0; q < 8; q++) {
            float4 hv = hp[q];
            acc0 = fmaf(hv.x, a_peer[4 * q + 0], acc0);
            acc1 = fmaf(hv.y, a_peer[4 * q + 1], acc1);
            acc0 = fmaf(hv.z, a_peer[4 * q + 2], acc0);
            acc1 = fmaf(hv.w, a_peer[4 * q + 3], acc1);
        }

        float sum = acc0 + acc1;
        sum += __shfl_xor_sync(0xffffffffu, sum, 1);
        sum += __shfl_xor_sync(0xffffffffu, sum, 2);

        if (c == 0) {
            float y = tanhf(sum + xb_cur);
            hbuf[wb][wr_idx] = y;                       // local STS
            if (s + 1 < T_LEN)                          // remote st.async + tx
                asm volatile(
                    "st.async.weak.shared::cluster.mbarrier::complete_tx::bytes.b32 "
                    "[%0], %1, [%2];"
                    :: "r"(p_addr[wb]), "r"(__float_as_uint(y)), "r"(p_bar[wb])
                    : "memory");
            hs[(size_t)s * H_DIM + col] = y;
            xb_cur = xb_nxt;
        }
        __syncthreads();   // local half of hbuf[wb] visible to all warps
    }

    // no CTA may exit while peer st.async traffic could be in flight
    asm volatile("barrier.cluster.arrive.aligned;" ::: "memory");
    asm volatile("barrier.cluster.wait.aligned;" ::: "memory");
}

// ---------------------------------------------------------------------------
extern "C" void kernel_launch(void* const* d_in, const int* in_sizes, int n_in,
                              void* d_out, int out_size) {
    const float* x  = (const float*)d_in[0];   // [32,2048,128]
    const float* A  = (const float*)d_in[1];   // [256,256]
    const float* Bm = (const float*)d_in[2];   // [128,256]
    const float* C  = (const float*)d_in[3];   // [256,256]
    float* out = (float*)d_out;                // [32,2048,256]

    float* xBp = nullptr;
    float* hsp = nullptr;
    cudaGetSymbolAddress((void**)&xBp, g_xB);
    cudaGetSymbolAddress((void**)&hsp, g_hs);

    // 1) xB = x @ Bm : [65536,128] @ [128,256]
    gemm_kernel<<<dim3(N_TOK / 128, H_DIM / 64), 256>>>(x, Bm, xBp, N_TOK, I_DIM, H_DIM);
    // 2) sequential scan: 2-CTA cluster per batch, split-phase overlap
    scan_kernel<<<B_SZ * 2, 512>>>(A);
    // 3) out = hs @ C : [65536,256] @ [256,256]
    gemm_kernel<<<dim3(N_TOK / 128, H_DIM / 64), 256>>>(hsp, C, out, N_TOK, H_DIM, H_DIM);
}

// round 10
// speedup vs baseline: 1.6382x; 1.6382x over previous
#include <cuda_runtime.h>
#include <cstdint>
#include <math.h>

#define B_SZ  32
#define T_LEN 2048
#define I_DIM 128
#define H_DIM 256
#define N_TOK (B_SZ * T_LEN)   // 65536

// Scratch (device globals: allocation-free rule)
__device__ float g_xB[(size_t)N_TOK * H_DIM];   // 64 MB
__device__ float g_hs[(size_t)N_TOK * H_DIM];   // 64 MB

// ---------------------------------------------------------------------------
// helpers
// ---------------------------------------------------------------------------
__device__ __forceinline__ uint32_t smem_u32(const void* p) {
    uint32_t a;
    asm("{ .reg .u64 t; cvta.to.shared.u64 t, %1; cvt.u32.u64 %0, t; }"
        : "=r"(a) : "l"(p));
    return a;
}
__device__ __forceinline__ void mbar_wait(uint32_t mbar, uint32_t parity) {
    asm volatile(
        "{\n\t.reg .pred P;\n\t"
        "WAITLOOP_%=:\n\t"
        "mbarrier.try_wait.parity.acquire.cta.shared::cta.b64 P, [%0], %1, 0x989680;\n\t"
        "@P bra.uni WAITDONE_%=;\n\t"
        "bra.uni WAITLOOP_%=;\n\t"
        "WAITDONE_%=:\n\t}"
        :: "r"(mbar), "r"(parity) : "memory");
}
__device__ __forceinline__ float tanh_fast(float x) {
    float y;
    asm("tanh.approx.f32 %0, %1;" : "=f"(y) : "f"(x));
    return y;
}

// ---------------------------------------------------------------------------
// fp32 tiled GEMM (scalar FFMA): Y[M,N] = X[M,K] @ W[K,N]
// BM=128, BN=64, BK=16, 256 threads, 8x4 micro-tile per thread.
// ---------------------------------------------------------------------------
__global__ void __launch_bounds__(256) gemm_kernel(const float* __restrict__ X,
                                                   const float* __restrict__ W,
                                                   float* __restrict__ Y,
                                                   int M, int K, int N) {
    __shared__ float Xs[16][128];
    __shared__ float Ws[16][64];

    const int tid = threadIdx.x;
    const int m0 = blockIdx.x * 128;
    const int n0 = blockIdx.y * 64;
    const int tx = tid & 15;
    const int ty = tid >> 4;

    float acc[8][4];
#pragma unroll
    for (int r = 0; r < 8; r++)
#pragma unroll
        for (int cc = 0; cc < 4; cc++) acc[r][cc] = 0.f;

    const int lrow  = tid >> 1;
    const int lpart = (tid & 1) * 8;

    for (int kt = 0; kt < K; kt += 16) {
        const float* xp = X + (size_t)(m0 + lrow) * K + kt + lpart;
        float4 v0 = *(const float4*)(xp);
        float4 v1 = *(const float4*)(xp + 4);
        Xs[lpart + 0][lrow] = v0.x;
        Xs[lpart + 1][lrow] = v0.y;
        Xs[lpart + 2][lrow] = v0.z;
        Xs[lpart + 3][lrow] = v0.w;
        Xs[lpart + 4][lrow] = v1.x;
        Xs[lpart + 5][lrow] = v1.y;
        Xs[lpart + 6][lrow] = v1.z;
        Xs[lpart + 7][lrow] = v1.w;
        {
            const int wk = tid >> 4;
            const int wn = (tid & 15) * 4;
            float4 wv = *(const float4*)(W + (size_t)(kt + wk) * N + n0 + wn);
            *(float4*)&Ws[wk][wn] = wv;
        }
        __syncthreads();

#pragma unroll
        for (int k = 0; k < 16; k++) {
            float4 xa = *(const float4*)&Xs[k][ty * 8];
            float4 xb = *(const float4*)&Xs[k][ty * 8 + 4];
            float4 wv = *(const float4*)&Ws[k][tx * 4];
            float xr[8] = {xa.x, xa.y, xa.z, xa.w, xb.x, xb.y, xb.z, xb.w};
            float wr[4] = {wv.x, wv.y, wv.z, wv.w};
#pragma unroll
            for (int r = 0; r < 8; r++)
#pragma unroll
                for (int cc = 0; cc < 4; cc++)
                    acc[r][cc] = fmaf(xr[r], wr[cc], acc[r][cc]);
        }
        __syncthreads();
    }

#pragma unroll
    for (int r = 0; r < 8; r++) {
        float4 o = make_float4(acc[r][0], acc[r][1], acc[r][2], acc[r][3]);
        *(float4*)&Y[(size_t)(m0 + ty * 8 + r) * N + n0 + tx * 4] = o;
    }
}

// ---------------------------------------------------------------------------
// Scan kernel: 4-CTA cluster per batch (128 CTAs, 256 threads each).
// CTA rank owns cols [rank*64, rank*64+64). Thread (g = tid>>2, c = tid&3):
// col = rank*64 + g, k-window [c*64, c*64+64). A slice (64 floats) in regs.
// h TRIPLE-buffered (race-free across cluster skew: a peer's send at step t
// implies all its warps passed sync(t-2), so buffer (t+1)%3 has no readers).
// Producers (c==0, 64 threads) st.async their h value to the 3 peers;
// expect_tx = 768 B per step. Skew 64+4 floats per block: the 4 c-window
// reads per warp instr land on banks {0,4,8,12} -> 1 phase per LDS.128.
// ---------------------------------------------------------------------------
#define HBLK 68
#define HB   (4 * HBLK)               // 272 floats per buffer
#define TXB  (3 * 64 * 4)             // 768 B incoming per step

__global__ void __launch_bounds__(256, 1) __cluster_dims__(4, 1, 1)
scan_kernel(const float* __restrict__ A) {
    __shared__ __align__(16) float hbuf[3][HB];
    __shared__ __align__(8) unsigned long long bars[3];

    const int tid = threadIdx.x;
    uint32_t rank;
    asm("mov.u32 %0, %%cluster_ctarank;" : "=r"(rank));
    const int b   = blockIdx.x >> 2;
    const int g   = tid >> 2;            // 0..63
    const int c   = tid & 3;             // 0..3
    const int col = (int)rank * 64 + g;
    const int k0  = c * 64;

    // A slice fully into registers: A[k0+k][col], k in [0,64)
    float a[64];
    {
        const float* Ac = A + (size_t)k0 * H_DIM + col;
#pragma unroll
        for (int k = 0; k < 64; k++) a[k] = Ac[(size_t)k * H_DIM];
    }

    const uint32_t bar0 = smem_u32(&bars[0]);
    if (tid == 0) {
#pragma unroll
        for (int i = 0; i < 3; i++)
            asm volatile("mbarrier.init.shared.b64 [%0], 1;"
                         :: "r"(bar0 + 8u * i) : "memory");
    }
    for (int i = tid; i < 3 * HB; i += 256) ((float*)hbuf)[i] = 0.f;
    __syncthreads();
    asm volatile("barrier.cluster.arrive.aligned;" ::: "memory");
    asm volatile("barrier.cluster.wait.aligned;" ::: "memory");

    // my column's slot index (same in every CTA's buffers)
    const int wr_idx = (int)rank * HBLK + g;
    // peer base addresses (buffer 0 slot + bar 0); offsets added per step
    uint32_t p_slot0[3], p_bar0[3];
    {
        uint32_t my_slot0 = smem_u32(&hbuf[0][wr_idx]);
#pragma unroll
        for (int p = 0; p < 3; p++) {
            uint32_t pr = (rank + 1u + p) & 3u;
            asm("mapa.shared::cluster.u32 %0, %1, %2;" : "=r"(p_slot0[p]) : "r"(my_slot0), "r"(pr));
            asm("mapa.shared::cluster.u32 %0, %1, %2;" : "=r"(p_bar0[p])  : "r"(bar0), "r"(pr));
        }
    }

    const float* xB = g_xB + (size_t)b * T_LEN * H_DIM;
    float*       hs = g_hs + (size_t)b * T_LEN * H_DIM;
    const int rd_off = c * HBLK;

    float xb_cur = (c == 0) ? xB[col] : 0.f;

    int rb = 0;                // s % 3
    for (int s = 0; s < T_LEN; s++) {
        const int wb = (rb == 2) ? 0 : rb + 1;

        // arm bar[wb] for this step's incoming 768 B
        if (tid == 0 && s + 1 < T_LEN)
            asm volatile("mbarrier.arrive.expect_tx.shared.b64 _, [%0], %1;"
                         :: "r"(bar0 + 8u * wb), "r"((uint32_t)TXB) : "memory");

        float xb_nxt = xb_cur;
        if (c == 0 && s + 1 < T_LEN)
            xb_nxt = xB[(size_t)(s + 1) * H_DIM + col];

        // wait for the 3 peers' h of buffer rb (sent during step s-1)
        if (s > 0)
            mbar_wait(bar0 + 8u * rb, (uint32_t)(((s - 1) / 3) & 1));

        // dot over this thread's 64-k window
        const float4* hp = (const float4*)(&hbuf[rb][rd_off]);
        float acc0 = 0.f, acc1 = 0.f;
#pragma unroll
        for (int q = 0; q < 16; q++) {
            float4 hv = hp[q];
            acc0 = fmaf(hv.x, a[4 * q + 0], acc0);
            acc1 = fmaf(hv.y, a[4 * q + 1], acc1);
            acc0 = fmaf(hv.z, a[4 * q + 2], acc0);
            acc1 = fmaf(hv.w, a[4 * q + 3], acc1);
        }
        float sum = acc0 + acc1;
        sum += __shfl_xor_sync(0xffffffffu, sum, 1);
        sum += __shfl_xor_sync(0xffffffffu, sum, 2);

        if (c == 0) {
            float y = tanh_fast(sum + xb_cur);
            hbuf[wb][wr_idx] = y;                     // local slot
            if (s + 1 < T_LEN) {
                uint32_t yb = __float_as_uint(y);
                uint32_t soff = (uint32_t)(wb * HB * 4);
                uint32_t boff = 8u * (uint32_t)wb;
#pragma unroll
                for (int p = 0; p < 3; p++)
                    asm volatile(
                        "st.async.weak.shared::cluster.mbarrier::complete_tx::bytes.b32 "
                        "[%0], %1, [%2];"
                        :: "r"(p_slot0[p] + soff), "r"(yb), "r"(p_bar0[p] + boff)
                        : "memory");
            }
            hs[(size_t)s * H_DIM + col] = y;
            xb_cur = xb_nxt;
        }
        __syncthreads();   // local writes to hbuf[wb] visible CTA-wide
        rb = wb;
    }

    // no CTA may exit while peer st.async traffic could be in flight
    asm volatile("barrier.cluster.arrive.aligned;" ::: "memory");
    asm volatile("barrier.cluster.wait.aligned;" ::: "memory");
}

// ---------------------------------------------------------------------------
extern "C" void kernel_launch(void* const* d_in, const int* in_sizes, int n_in,
                              void* d_out, int out_size) {
    const float* x  = (const float*)d_in[0];   // [32,2048,128]
    const float* A  = (const float*)d_in[1];   // [256,256]
    const float* Bm = (const float*)d_in[2];   // [128,256]
    const float* C  = (const float*)d_in[3];   // [256,256]
    float* out = (float*)d_out;                // [32,2048,256]

    float* xBp = nullptr;
    float* hsp = nullptr;
    cudaGetSymbolAddress((void**)&xBp, g_xB);
    cudaGetSymbolAddress((void**)&hsp, g_hs);

    // 1) xB = x @ Bm : [65536,128] @ [128,256]
    gemm_kernel<<<dim3(N_TOK / 128, H_DIM / 64), 256>>>(x, Bm, xBp, N_TOK, I_DIM, H_DIM);
    // 2) sequential scan: 4-CTA cluster per batch, triple-buffered h exchange
    scan_kernel<<<B_SZ * 4, 256>>>(A);
    // 3) out = hs @ C : [65536,256] @ [256,256]
    gemm_kernel<<<dim3(N_TOK / 128, H_DIM / 64), 256>>>(hsp, C, out, N_TOK, H_DIM, H_DIM);
}